// round 15
// baseline (speedup 1.0000x reference)
#include <cuda_runtime.h>
#include <cuda_fp16.h>
#include <cstdint>

// Block-diagonal equivariant linear, (n,i)-row formulation, mma.sync fp16.
// For block l (d in {1,3,5}, off {0,128,512}), r = n*d + i:
//   A[r][u] = x[n][off+u*d+i];  O[r][w] = sum_u A[r][u]*W[u][w]*ALPHA
// Per 64-row tile: M=64,N=128,K=128 GEMM, single-pass fp16, fp32 accumulate.
// W fragments live in registers for the whole tile loop.
// NEW (R14): x gathered via cp.async into a contiguous SMEM mirror (full MLP,
// no register cost, overlapped across mainloop+epilogue); the fp16 convert/
// transpose reads the mirror with short-latency LDS instead of raw LDG.

#define FEATS 1152
#define NT 256
#define PLE 136                        // fp16 elems per A-plane row
#define ABUF (64 * PLE * 2)            // one A buffer = 17408 B
#define OFF_MIR (2 * ABUF)             // x mirror (contiguous float4 tasks)
#define MIR_BYTES 36096
#define OFF_ST (OFF_MIR + MIR_BYTES)   // union: W stage / out stage
#define STAGE_BYTES 36096
#define SMEM_BYTES (OFF_ST + STAGE_BYTES)   // 107008
#define ALPHA_F 0.08838834764831845f   // 1/sqrt(128)

__device__ __forceinline__ void mma16816h(float* c, const uint32_t* a,
                                          uint32_t b0, uint32_t b1) {
    asm volatile(
        "mma.sync.aligned.m16n8k16.row.col.f32.f16.f16.f32 "
        "{%0,%1,%2,%3}, {%4,%5,%6,%7}, {%8,%9}, {%0,%1,%2,%3};"
        : "+f"(c[0]), "+f"(c[1]), "+f"(c[2]), "+f"(c[3])
        : "r"(a[0]), "r"(a[1]), "r"(a[2]), "r"(a[3]), "r"(b0), "r"(b1));
}

__device__ __forceinline__ void ldmx4(uint32_t* r, uint32_t a) {
    asm volatile("ldmatrix.sync.aligned.m8n8.x4.shared.b16 {%0,%1,%2,%3}, [%4];"
                 : "=r"(r[0]), "=r"(r[1]), "=r"(r[2]), "=r"(r[3]) : "r"(a));
}

__device__ __forceinline__ void sts16(uint32_t a, uint32_t v) {
    asm volatile("st.shared.u16 [%0], %1;" :: "r"(a), "r"(v));
}
__device__ __forceinline__ void sts64v(uint32_t a, uint32_t v0, uint32_t v1) {
    asm volatile("st.shared.v2.u32 [%0], {%1,%2};" :: "r"(a), "r"(v0), "r"(v1));
}
__device__ __forceinline__ void cpasync16(uint32_t dst, const void* src, int sz) {
    asm volatile("cp.async.cg.shared.global [%0], [%1], 16, %2;\n"
                 :: "r"(dst), "l"(src), "r"(sz));
}

// Issue cp.async gather of one tile's x rows into the contiguous mirror.
template <int D, int OFF>
__device__ __forceinline__ void issue_mirror(
    uint32_t MIR, const float* __restrict__ x, int ktile, int ntot, int tid)
{
    const int fr0 = ktile << 6;
    const int fn0 = fr0 / D;
    const int fn1r = (fr0 + 63) / D + 1;          // unclipped row count
    const int ft = (fn1r - fn0) * 32 * D;         // float4 tasks
    for (int t = tid; t < ft; t += NT) {
        const int nnr = t / (32 * D);
        const int c4 = t - nnr * (32 * D);
        const int nn = fn0 + nnr;
        const int sz = (nn < ntot) ? 16 : 0;      // sz=0 -> 16B zero-fill
        cpasync16(MIR + (uint32_t)t * 16u,
                  x + (long)nn * FEATS + OFF + 4 * c4, sz);
    }
    asm volatile("cp.async.commit_group;\n");
}

// Convert mirror -> fp16 A plane (transpose scatter, short-latency LDS only).
template <int D>
__device__ __forceinline__ void convert_tile(
    uint32_t AS, const float* __restrict__ mir, int ktile, int tid)
{
    const int fr0 = ktile << 6;
    const int fn0 = fr0 / D;
    const int fn1r = (fr0 + 63) / D + 1;
    const int ft = (fn1r - fn0) * 32 * D;
    for (int t = tid; t < ft; t += NT) {
        const float4 v = *reinterpret_cast<const float4*>(mir + 4 * t);
        const int nnr = t / (32 * D);
        const int c4 = t - nnr * (32 * D);
        if (D == 1) {
            const int rr = nnr;
            __half2 h01 = __floats2half2_rn(v.x, v.y);
            __half2 h23 = __floats2half2_rn(v.z, v.w);
            sts64v(AS + (uint32_t)(rr * PLE + 4 * c4) * 2u,
                   *reinterpret_cast<uint32_t*>(&h01),
                   *reinterpret_cast<uint32_t*>(&h23));
        } else {
            const int rr0 = (fn0 + nnr) * D - fr0;
            const float vv[4] = {v.x, v.y, v.z, v.w};
#pragma unroll
            for (int e = 0; e < 4; e++) {
                const int cc = 4 * c4 + e;
                const int u = cc / D;
                const int rr = rr0 + (cc - u * D);
                if ((unsigned)rr < 64u)
                    sts16(AS + (uint32_t)(rr * PLE + u) * 2u,
                          (uint32_t)__half_as_ushort(__float2half_rn(vv[e])));
            }
        }
    }
}

template <int D, int OFF>
__device__ __forceinline__ void run_block(
    const float* __restrict__ x, const float* __restrict__ w,
    float* __restrict__ out, int ntot, int cidx, int ccnt)
{
    constexpr int SN = 128 * D + 4;    // stage floats per n-row
    extern __shared__ unsigned char smem[];
    const uint32_t smem_u32 = (uint32_t)__cvta_generic_to_shared(smem);
    const uint32_t MIR = smem_u32 + OFF_MIR;
    const uint32_t WS  = smem_u32 + OFF_ST;
    const float* mirf = reinterpret_cast<const float*>(smem + OFF_MIR);
    __half* Wp   = reinterpret_cast<__half*>(smem + OFF_ST);
    float* stage = reinterpret_cast<float*>(smem + OFF_ST);
    const int tid = threadIdx.x;

    const int ntiles = (ntot * D + 63) >> 6;
    const int nloc = (ntiles - cidx + ccnt - 1) / ccnt;
    if (nloc <= 0) return;

    // ---- Stage W^T fp16 (ALPHA folded) into union region ----
    for (int idx = tid; idx < 128 * 128; idx += NT) {
        int u = idx >> 7, ww = idx & 127;
        Wp[ww * PLE + u] = __float2half_rn(w[idx] * ALPHA_F);
    }
    // kick off the first tile's gather while W is being staged/read
    issue_mirror<D, OFF>(MIR, x, cidx, ntot, tid);
    __syncthreads();   // W staged

    // ---- Warp geometry (2m x 4n grid, warp tile m32 x n32) ----
    const int warp = tid >> 5;
    const int lane = tid & 31;
    const int m0 = (warp & 1) * 32;
    const int n0 = (warp >> 1) * 32;
    const int arow = (lane & 7) | (lane & 8);
    const int akc  = (lane >> 4) << 3;
    const int brow = (lane & 7) | ((lane & 16) >> 1);
    const int bkc  = lane & 8;
    int aoff[2];
#pragma unroll
    for (int mi = 0; mi < 2; mi++)
        aoff[mi] = ((m0 + mi * 16 + arow) * PLE + akc) * 2;

    // ---- Load ALL W fragments into registers (constant across tiles) ----
    uint32_t wr[64];
#pragma unroll
    for (int ks = 0; ks < 8; ks++)
#pragma unroll
        for (int jc = 0; jc < 2; jc++)
            ldmx4(&wr[ks * 8 + jc * 4],
                  WS + (uint32_t)(((n0 + jc * 16 + brow) * PLE + bkc) * 2 + ks * 32));

    asm volatile("cp.async.wait_group 0;\n");
    __syncthreads();   // wr reads done (stage free); mirror(tile0) visible
    convert_tile<D>(smem_u32, mirf, cidx, tid);
    __syncthreads();   // A(0) ready; mirror free

    const int g = lane >> 2, tq = lane & 3;

    for (int j = 0; j < nloc; j++) {
        const uint32_t AS = smem_u32 + (uint32_t)(j & 1) * ABUF;
        const int kt = cidx + j * ccnt;
        const int r0 = kt << 6;
        const int en0 = r0 / D;
        int en1 = (r0 + 63) / D + 1; if (en1 > ntot) en1 = ntot;

        // ---- Issue next tile's gather (overlaps mainloop + epilogue) ----
        if (j + 1 < nloc)
            issue_mirror<D, OFF>(MIR, x, cidx + (j + 1) * ccnt, ntot, tid);

        // ---- MMA mainloop: 2 ldmatrix + 8 HMMA per k-step ----
        float acc[2][4][4];
#pragma unroll
        for (int mi = 0; mi < 2; mi++)
#pragma unroll
            for (int jn = 0; jn < 4; jn++)
#pragma unroll
                for (int r = 0; r < 4; r++) acc[mi][jn][r] = 0.0f;

#pragma unroll
        for (int ks = 0; ks < 8; ks++) {
            const int kb2 = ks * 32;
            uint32_t a0[4], a1[4];
            ldmx4(a0, AS + aoff[0] + kb2);
            ldmx4(a1, AS + aoff[1] + kb2);
#pragma unroll
            for (int jc = 0; jc < 2; jc++) {
                const uint32_t* bw = &wr[ks * 8 + jc * 4];
                mma16816h(acc[0][2 * jc],     a0, bw[0], bw[1]);
                mma16816h(acc[1][2 * jc],     a1, bw[0], bw[1]);
                mma16816h(acc[0][2 * jc + 1], a0, bw[2], bw[3]);
                mma16816h(acc[1][2 * jc + 1], a1, bw[2], bw[3]);
            }
        }

        // ---- Epilogue 1: acc -> stage in x-layout (stage[nnloc][cc]) ----
        int rbase[4];
#pragma unroll
        for (int q = 0; q < 4; q++) {
            const int row = m0 + (q >> 1) * 16 + g + (q & 1) * 8;
            const int gr = r0 + row;
            const int nq = gr / D;
            rbase[q] = (nq - en0) * SN + (gr - nq * D);
        }
#pragma unroll
        for (int mi = 0; mi < 2; mi++) {
#pragma unroll
            for (int jn = 0; jn < 4; jn++) {
                const int col = n0 + 8 * jn + 2 * tq;
                if (D == 1) {
                    *reinterpret_cast<float2*>(stage + rbase[2 * mi] + col) =
                        make_float2(acc[mi][jn][0], acc[mi][jn][1]);
                    *reinterpret_cast<float2*>(stage + rbase[2 * mi + 1] + col) =
                        make_float2(acc[mi][jn][2], acc[mi][jn][3]);
                } else {
                    stage[rbase[2 * mi] + col * D]           = acc[mi][jn][0];
                    stage[rbase[2 * mi] + (col + 1) * D]     = acc[mi][jn][1];
                    stage[rbase[2 * mi + 1] + col * D]       = acc[mi][jn][2];
                    stage[rbase[2 * mi + 1] + (col + 1) * D] = acc[mi][jn][3];
                }
            }
        }
        __syncthreads();

        // ---- Epilogue 2: contiguous stage -> gmem float4 copy ----
        {
            const int et = (en1 - en0) * 32 * D;
            for (int t = tid; t < et; t += NT) {
                const int nnr = t / (32 * D);
                const int c4 = t - nnr * (32 * D);
                const int nn = en0 + nnr;
                float* gp = out + (long)nn * FEATS + OFF + 4 * c4;
                const float* sp = stage + nnr * SN + 4 * c4;
                if (D == 1) {
                    *reinterpret_cast<float4*>(gp) =
                        *reinterpret_cast<const float4*>(sp);
                } else {
                    const bool full = (nn * D >= r0) && ((nn + 1) * D <= r0 + 64);
                    if (full) {
                        *reinterpret_cast<float4*>(gp) =
                            *reinterpret_cast<const float4*>(sp);
                    } else {
#pragma unroll
                        for (int e = 0; e < 4; e++) {
                            const int cc = 4 * c4 + e;
                            const int u = cc / D;
                            const int rr = nn * D + (cc - u * D) - r0;
                            if ((unsigned)rr < 64u) gp[e] = sp[e];
                        }
                    }
                }
            }
        }

        // ---- Convert next tile: mirror -> A plane (short-latency LDS) ----
        asm volatile("cp.async.wait_group 0;\n");
        __syncthreads();   // stage consumed by all; mirror data visible
        if (j + 1 < nloc)
            convert_tile<D>(smem_u32 + (uint32_t)((j + 1) & 1) * ABUF,
                            mirf, cidx + (j + 1) * ccnt, tid);
        __syncthreads();   // A(j+1) ready; mirror free for next issue
    }
}

__global__ __launch_bounds__(NT, 2)
void Linear_36146444763339_kernel(
    const float* __restrict__ x,
    const float* __restrict__ w0,
    const float* __restrict__ w1,
    const float* __restrict__ w2,
    float* __restrict__ out,
    int ntot)
{
    const int bx = blockIdx.x;
    if (bx < 34)       run_block<1, 0>  (x, w0, out, ntot, bx,       34);
    else if (bx < 132) run_block<3, 128>(x, w1, out, ntot, bx - 34,  98);
    else               run_block<5, 512>(x, w2, out, ntot, bx - 132, 164);
}

extern "C" void kernel_launch(void* const* d_in, const int* in_sizes, int n_in,
                              void* d_out, int out_size) {
    const float* x  = (const float*)d_in[0];
    const float* w0 = (const float*)d_in[1];
    const float* w1 = (const float*)d_in[2];
    const float* w2 = (const float*)d_in[3];
    float* out = (float*)d_out;
    const int ntot = in_sizes[0] / FEATS;

    cudaFuncSetAttribute(Linear_36146444763339_kernel,
                         cudaFuncAttributeMaxDynamicSharedMemorySize, SMEM_BYTES);

    Linear_36146444763339_kernel<<<296, NT, SMEM_BYTES>>>(x, w0, w1, w2, out, ntot);
}

// round 16
// speedup vs baseline: 1.0277x; 1.0277x over previous
#include <cuda_runtime.h>
#include <cuda_fp16.h>
#include <cstdint>

// Block-diagonal equivariant linear, (n,i)-row formulation, mma.sync fp16.
// For block l (d in {1,3,5}, off {0,128,512}), r = n*d + i:
//   A[r][u] = x[n][off+u*d+i];  O[r][w] = sum_u A[r][u]*W[u][w]*ALPHA
// Per 64-row tile: M=64,N=128,K=128 GEMM, single-pass fp16, fp32 accumulate.
// W fragments live in registers for the whole tile loop.
// R15: two barrier phases per tile (epi2 + next-tile convert merged);
// wrap-increment index strength reduction in all streaming loops.

#define FEATS 1152
#define NT 256
#define PLE 136                        // fp16 elems per A-plane row
#define ABUF (64 * PLE * 2)            // one A buffer = 17408 B
#define OFF_MIR (2 * ABUF)             // x mirror (contiguous float4 tasks)
#define MIR_BYTES 36096
#define OFF_ST (OFF_MIR + MIR_BYTES)   // union: W stage / out stage
#define STAGE_BYTES 36096
#define SMEM_BYTES (OFF_ST + STAGE_BYTES)   // 107008
#define ALPHA_F 0.08838834764831845f   // 1/sqrt(128)

__device__ __forceinline__ void mma16816h(float* c, const uint32_t* a,
                                          uint32_t b0, uint32_t b1) {
    asm volatile(
        "mma.sync.aligned.m16n8k16.row.col.f32.f16.f16.f32 "
        "{%0,%1,%2,%3}, {%4,%5,%6,%7}, {%8,%9}, {%0,%1,%2,%3};"
        : "+f"(c[0]), "+f"(c[1]), "+f"(c[2]), "+f"(c[3])
        : "r"(a[0]), "r"(a[1]), "r"(a[2]), "r"(a[3]), "r"(b0), "r"(b1));
}

__device__ __forceinline__ void ldmx4(uint32_t* r, uint32_t a) {
    asm volatile("ldmatrix.sync.aligned.m8n8.x4.shared.b16 {%0,%1,%2,%3}, [%4];"
                 : "=r"(r[0]), "=r"(r[1]), "=r"(r[2]), "=r"(r[3]) : "r"(a));
}

__device__ __forceinline__ void sts16(uint32_t a, uint32_t v) {
    asm volatile("st.shared.u16 [%0], %1;" :: "r"(a), "r"(v));
}
__device__ __forceinline__ void sts64v(uint32_t a, uint32_t v0, uint32_t v1) {
    asm volatile("st.shared.v2.u32 [%0], {%1,%2};" :: "r"(a), "r"(v0), "r"(v1));
}
__device__ __forceinline__ void cpasync16(uint32_t dst, const void* src, int sz) {
    asm volatile("cp.async.cg.shared.global [%0], [%1], 16, %2;\n"
                 :: "r"(dst), "l"(src), "r"(sz));
}

// Issue cp.async gather of one tile's x rows into the contiguous mirror.
template <int D, int OFF>
__device__ __forceinline__ void issue_mirror(
    uint32_t MIR, const float* __restrict__ x, int ktile, int ntot, int tid)
{
    constexpr int C4N = 32 * D;
    constexpr int DN = NT / C4N;
    constexpr int DC = NT - DN * C4N;
    const int fr0 = ktile << 6;
    const int fn0 = fr0 / D;
    const int ft = ((fr0 + 63) / D + 1 - fn0) * C4N;
    int nnr = tid / C4N;
    int c4 = tid - nnr * C4N;
    const float* base = x + (long)fn0 * FEATS + OFF;
    for (int t = tid; t < ft; t += NT) {
        const int nn = fn0 + nnr;
        const int sz = (nn < ntot) ? 16 : 0;      // sz=0 -> 16B zero-fill
        cpasync16(MIR + (uint32_t)t * 16u, base + (long)nnr * FEATS + 4 * c4, sz);
        nnr += DN; c4 += DC;
        if (c4 >= C4N) { c4 -= C4N; nnr++; }
    }
    asm volatile("cp.async.commit_group;\n");
}

// Convert mirror -> fp16 A plane (transpose scatter, short-latency LDS only).
template <int D>
__device__ __forceinline__ void convert_tile(
    uint32_t AS, const float* __restrict__ mir, int ktile, int tid)
{
    constexpr int C4N = 32 * D;
    constexpr int DN = NT / C4N;
    constexpr int DC = NT - DN * C4N;
    const int fr0 = ktile << 6;
    const int fn0 = fr0 / D;
    const int ft = ((fr0 + 63) / D + 1 - fn0) * C4N;
    int nnr = tid / C4N;
    int c4 = tid - nnr * C4N;
    for (int t = tid; t < ft; t += NT) {
        const float4 v = *reinterpret_cast<const float4*>(mir + 4 * t);
        if (D == 1) {
            __half2 h01 = __floats2half2_rn(v.x, v.y);
            __half2 h23 = __floats2half2_rn(v.z, v.w);
            sts64v(AS + (uint32_t)(nnr * PLE + 4 * c4) * 2u,
                   *reinterpret_cast<uint32_t*>(&h01),
                   *reinterpret_cast<uint32_t*>(&h23));
        } else {
            const int rr0 = (fn0 + nnr) * D - fr0;
            const float vv[4] = {v.x, v.y, v.z, v.w};
            int u = (4 * c4) / D;
            int ii = 4 * c4 - u * D;
#pragma unroll
            for (int e = 0; e < 4; e++) {
                const int rr = rr0 + ii;
                if ((unsigned)rr < 64u)
                    sts16(AS + (uint32_t)(rr * PLE + u) * 2u,
                          (uint32_t)__half_as_ushort(__float2half_rn(vv[e])));
                if (++ii == D) { ii = 0; u++; }
            }
        }
        nnr += DN; c4 += DC;
        if (c4 >= C4N) { c4 -= C4N; nnr++; }
    }
}

template <int D, int OFF>
__device__ __forceinline__ void run_block(
    const float* __restrict__ x, const float* __restrict__ w,
    float* __restrict__ out, int ntot, int cidx, int ccnt)
{
    constexpr int SN = 128 * D + 4;    // stage floats per n-row
    constexpr int C4N = 32 * D;
    constexpr int DN = NT / C4N;
    constexpr int DC = NT - DN * C4N;
    extern __shared__ unsigned char smem[];
    const uint32_t smem_u32 = (uint32_t)__cvta_generic_to_shared(smem);
    const uint32_t MIR = smem_u32 + OFF_MIR;
    const uint32_t WS  = smem_u32 + OFF_ST;
    const float* mirf = reinterpret_cast<const float*>(smem + OFF_MIR);
    __half* Wp   = reinterpret_cast<__half*>(smem + OFF_ST);
    float* stage = reinterpret_cast<float*>(smem + OFF_ST);
    const int tid = threadIdx.x;

    const int ntiles = (ntot * D + 63) >> 6;
    const int nloc = (ntiles - cidx + ccnt - 1) / ccnt;
    if (nloc <= 0) return;

    // ---- Prologue: gather tile 0; stage W^T fp16 (ALPHA folded) ----
    issue_mirror<D, OFF>(MIR, x, cidx, ntot, tid);
    for (int idx = tid; idx < 128 * 128; idx += NT) {
        int u = idx >> 7, ww = idx & 127;
        Wp[ww * PLE + u] = __float2half_rn(w[idx] * ALPHA_F);
    }
    __syncthreads();   // W staged

    // ---- Warp geometry (2m x 4n grid, warp tile m32 x n32) ----
    const int warp = tid >> 5;
    const int lane = tid & 31;
    const int m0 = (warp & 1) * 32;
    const int n0 = (warp >> 1) * 32;
    const int arow = (lane & 7) | (lane & 8);
    const int akc  = (lane >> 4) << 3;
    const int brow = (lane & 7) | ((lane & 16) >> 1);
    const int bkc  = lane & 8;
    int aoff[2];
#pragma unroll
    for (int mi = 0; mi < 2; mi++)
        aoff[mi] = ((m0 + mi * 16 + arow) * PLE + akc) * 2;

    // ---- Load ALL W fragments into registers (constant across tiles) ----
    uint32_t wr[64];
#pragma unroll
    for (int ks = 0; ks < 8; ks++)
#pragma unroll
        for (int jc = 0; jc < 2; jc++)
            ldmx4(&wr[ks * 8 + jc * 4],
                  WS + (uint32_t)(((n0 + jc * 16 + brow) * PLE + bkc) * 2 + ks * 32));

    asm volatile("cp.async.wait_group 0;\n");
    __syncthreads();   // wr reads done (stage free); mirror(tile0) visible
    convert_tile<D>(smem_u32, mirf, cidx, tid);
    __syncthreads();   // A(0) ready; mirror free

    const int g = lane >> 2, tq = lane & 3;

    for (int j = 0; j < nloc; j++) {
        const uint32_t AS = smem_u32 + (uint32_t)(j & 1) * ABUF;
        const int kt = cidx + j * ccnt;
        const int r0 = kt << 6;
        const int en0 = r0 / D;
        int en1 = (r0 + 63) / D + 1; if (en1 > ntot) en1 = ntot;

        // ---- Issue next tile's gather (covered by mainloop + epi1) ----
        if (j + 1 < nloc)
            issue_mirror<D, OFF>(MIR, x, cidx + (j + 1) * ccnt, ntot, tid);

        // ---- MMA mainloop: 2 ldmatrix + 8 HMMA per k-step ----
        float acc[2][4][4];
#pragma unroll
        for (int mi = 0; mi < 2; mi++)
#pragma unroll
            for (int jn = 0; jn < 4; jn++)
#pragma unroll
                for (int r = 0; r < 4; r++) acc[mi][jn][r] = 0.0f;

#pragma unroll
        for (int ks = 0; ks < 8; ks++) {
            const int kb2 = ks * 32;
            uint32_t a0[4], a1[4];
            ldmx4(a0, AS + aoff[0] + kb2);
            ldmx4(a1, AS + aoff[1] + kb2);
#pragma unroll
            for (int jc = 0; jc < 2; jc++) {
                const uint32_t* bw = &wr[ks * 8 + jc * 4];
                mma16816h(acc[0][2 * jc],     a0, bw[0], bw[1]);
                mma16816h(acc[1][2 * jc],     a1, bw[0], bw[1]);
                mma16816h(acc[0][2 * jc + 1], a0, bw[2], bw[3]);
                mma16816h(acc[1][2 * jc + 1], a1, bw[2], bw[3]);
            }
        }

        // ---- Epilogue 1: acc -> stage in x-layout (stage[nnloc][cc]) ----
        int rbase[4];
#pragma unroll
        for (int q = 0; q < 4; q++) {
            const int row = m0 + (q >> 1) * 16 + g + (q & 1) * 8;
            const int gr = r0 + row;
            const int nq = gr / D;
            rbase[q] = (nq - en0) * SN + (gr - nq * D);
        }
#pragma unroll
        for (int mi = 0; mi < 2; mi++) {
#pragma unroll
            for (int jn = 0; jn < 4; jn++) {
                const int col = n0 + 8 * jn + 2 * tq;
                if (D == 1) {
                    *reinterpret_cast<float2*>(stage + rbase[2 * mi] + col) =
                        make_float2(acc[mi][jn][0], acc[mi][jn][1]);
                    *reinterpret_cast<float2*>(stage + rbase[2 * mi + 1] + col) =
                        make_float2(acc[mi][jn][2], acc[mi][jn][3]);
                } else {
                    stage[rbase[2 * mi] + col * D]           = acc[mi][jn][0];
                    stage[rbase[2 * mi] + (col + 1) * D]     = acc[mi][jn][1];
                    stage[rbase[2 * mi + 1] + col * D]       = acc[mi][jn][2];
                    stage[rbase[2 * mi + 1] + (col + 1) * D] = acc[mi][jn][3];
                }
            }
        }
        __syncthreads();                       // S1: stage complete
        asm volatile("cp.async.wait_group 0;\n");  // mirror(j+1) landed

        // ---- Merged phase: epi2 (stage -> gmem) + convert(j+1) ----
        {
            const int last = en1 - en0 - 1;
            const int et = (en1 - en0) * C4N;
            int nnr = tid / C4N;
            int c4 = tid - nnr * C4N;
            for (int t = tid; t < et; t += NT) {
                const int nn = en0 + nnr;
                float* gp = out + (long)nn * FEATS + OFF + 4 * c4;
                const float* sp = stage + nnr * SN + 4 * c4;
                if (D == 1) {
                    *reinterpret_cast<float4*>(gp) =
                        *reinterpret_cast<const float4*>(sp);
                } else {
                    const bool edge = (nnr == 0) | (nnr == last);
                    if (!edge) {
                        *reinterpret_cast<float4*>(gp) =
                            *reinterpret_cast<const float4*>(sp);
                    } else {
                        int u = (4 * c4) / D;
                        int ii = 4 * c4 - u * D;
#pragma unroll
                        for (int e = 0; e < 4; e++) {
                            const int rr = nn * D + ii - r0;
                            if ((unsigned)rr < 64u) gp[e] = sp[e];
                            if (++ii == D) { ii = 0; u++; }
                        }
                    }
                }
                nnr += DN; c4 += DC;
                if (c4 >= C4N) { c4 -= C4N; nnr++; }
            }
        }
        if (j + 1 < nloc)
            convert_tile<D>(smem_u32 + (uint32_t)((j + 1) & 1) * ABUF,
                            mirf, cidx + (j + 1) * ccnt, tid);
        __syncthreads();   // S2: stage consumed, A(j+1) ready, mirror free
    }
}

__global__ __launch_bounds__(NT, 2)
void Linear_36146444763339_kernel(
    const float* __restrict__ x,
    const float* __restrict__ w0,
    const float* __restrict__ w1,
    const float* __restrict__ w2,
    float* __restrict__ out,
    int ntot)
{
    const int bx = blockIdx.x;
    if (bx < 34)       run_block<1, 0>  (x, w0, out, ntot, bx,       34);
    else if (bx < 132) run_block<3, 128>(x, w1, out, ntot, bx - 34,  98);
    else               run_block<5, 512>(x, w2, out, ntot, bx - 132, 164);
}

extern "C" void kernel_launch(void* const* d_in, const int* in_sizes, int n_in,
                              void* d_out, int out_size) {
    const float* x  = (const float*)d_in[0];
    const float* w0 = (const float*)d_in[1];
    const float* w1 = (const float*)d_in[2];
    const float* w2 = (const float*)d_in[3];
    float* out = (float*)d_out;
    const int ntot = in_sizes[0] / FEATS;

    cudaFuncSetAttribute(Linear_36146444763339_kernel,
                         cudaFuncAttributeMaxDynamicSharedMemorySize, SMEM_BYTES);

    Linear_36146444763339_kernel<<<296, NT, SMEM_BYTES>>>(x, w0, w1, w2, out, ntot);
}

// round 17
// speedup vs baseline: 1.5873x; 1.5445x over previous
#include <cuda_runtime.h>
#include <cuda_fp16.h>
#include <cstdint>

// Block-diagonal equivariant linear, (n,i)-row formulation, mma.sync fp16.
// For block l (d in {1,3,5}, off {0,128,512}), r = n*d + i:
//   A[r][u] = x[n][off+u*d+i];  O[r][w] = sum_u A[r][u]*W[u][w]*ALPHA
// R16: M=32 tiles, NT=128, 4 CTAs/SM -> 4 independent barrier domains per SM
// (phase-serialization attack). Single A buffer (convert runs post-mainloop in
// the merged phase). W frags in registers; cp.async mirror; x-layout stage.

#define FEATS 1152
#define NT 128
#define PLE 136                        // fp16 elems per A-plane row
#define ABUF (32 * PLE * 2)            // A buffer = 8704 B
#define OFF_MIR ABUF                   // mirror at 8704, room to 34816
#define OFF_STG 34816                  // output stage (union covers W staging)
#define STG_BYTES 20608                // D=5 worst: 8 rows * 644 * 4
#define SMEM_BYTES (OFF_STG + STG_BYTES)   // 55424 -> 4 CTAs/SM
#define ALPHA_F 0.08838834764831845f   // 1/sqrt(128)

__device__ __forceinline__ void mma16816h(float* c, const uint32_t* a,
                                          uint32_t b0, uint32_t b1) {
    asm volatile(
        "mma.sync.aligned.m16n8k16.row.col.f32.f16.f16.f32 "
        "{%0,%1,%2,%3}, {%4,%5,%6,%7}, {%8,%9}, {%0,%1,%2,%3};"
        : "+f"(c[0]), "+f"(c[1]), "+f"(c[2]), "+f"(c[3])
        : "r"(a[0]), "r"(a[1]), "r"(a[2]), "r"(a[3]), "r"(b0), "r"(b1));
}

__device__ __forceinline__ void ldmx4(uint32_t* r, uint32_t a) {
    asm volatile("ldmatrix.sync.aligned.m8n8.x4.shared.b16 {%0,%1,%2,%3}, [%4];"
                 : "=r"(r[0]), "=r"(r[1]), "=r"(r[2]), "=r"(r[3]) : "r"(a));
}

__device__ __forceinline__ void sts16(uint32_t a, uint32_t v) {
    asm volatile("st.shared.u16 [%0], %1;" :: "r"(a), "r"(v));
}
__device__ __forceinline__ void sts64v(uint32_t a, uint32_t v0, uint32_t v1) {
    asm volatile("st.shared.v2.u32 [%0], {%1,%2};" :: "r"(a), "r"(v0), "r"(v1));
}
__device__ __forceinline__ void cpasync16(uint32_t dst, const void* src, int sz) {
    asm volatile("cp.async.cg.shared.global [%0], [%1], 16, %2;\n"
                 :: "r"(dst), "l"(src), "r"(sz));
}

// Issue cp.async gather of one 32-row tile into the contiguous mirror.
template <int D, int OFF>
__device__ __forceinline__ void issue_mirror(
    uint32_t MIR, const float* __restrict__ x, int ktile, int ntot, int tid)
{
    constexpr int C4N = 32 * D;
    constexpr int DN = NT / C4N;
    constexpr int DC = NT - DN * C4N;
    const int fr0 = ktile << 5;
    const int fn0 = fr0 / D;
    const int ft = ((fr0 + 31) / D + 1 - fn0) * C4N;
    int nnr = tid / C4N;
    int c4 = tid - nnr * C4N;
    const float* base = x + (long)fn0 * FEATS + OFF;
    for (int t = tid; t < ft; t += NT) {
        const int sz = (fn0 + nnr < ntot) ? 16 : 0;   // sz=0 -> 16B zero-fill
        cpasync16(MIR + (uint32_t)t * 16u, base + (long)nnr * FEATS + 4 * c4, sz);
        nnr += DN; c4 += DC;
        if (c4 >= C4N) { c4 -= C4N; nnr++; }
    }
    asm volatile("cp.async.commit_group;\n");
}

// Convert mirror -> fp16 A plane (each thread reads what it gathered).
template <int D>
__device__ __forceinline__ void convert_tile(
    uint32_t AS, const float* __restrict__ mir, int ktile, int tid)
{
    constexpr int C4N = 32 * D;
    constexpr int DN = NT / C4N;
    constexpr int DC = NT - DN * C4N;
    const int fr0 = ktile << 5;
    const int fn0 = fr0 / D;
    const int ft = ((fr0 + 31) / D + 1 - fn0) * C4N;
    int nnr = tid / C4N;
    int c4 = tid - nnr * C4N;
#pragma unroll 2
    for (int t = tid; t < ft; t += NT) {
        const float4 v = *reinterpret_cast<const float4*>(mir + 4 * t);
        if (D == 1) {
            __half2 h01 = __floats2half2_rn(v.x, v.y);
            __half2 h23 = __floats2half2_rn(v.z, v.w);
            sts64v(AS + (uint32_t)(nnr * PLE + 4 * c4) * 2u,
                   *reinterpret_cast<uint32_t*>(&h01),
                   *reinterpret_cast<uint32_t*>(&h23));
        } else {
            const int rr0 = (fn0 + nnr) * D - fr0;
            const float vv[4] = {v.x, v.y, v.z, v.w};
            int u = (4 * c4) / D;
            int ii = 4 * c4 - u * D;
#pragma unroll
            for (int e = 0; e < 4; e++) {
                const int rr = rr0 + ii;
                if ((unsigned)rr < 32u)
                    sts16(AS + (uint32_t)(rr * PLE + u) * 2u,
                          (uint32_t)__half_as_ushort(__float2half_rn(vv[e])));
                if (++ii == D) { ii = 0; u++; }
            }
        }
        nnr += DN; c4 += DC;
        if (c4 >= C4N) { c4 -= C4N; nnr++; }
    }
}

template <int D, int OFF>
__device__ __forceinline__ void run_block(
    const float* __restrict__ x, const float* __restrict__ w,
    float* __restrict__ out, int ntot, int cidx, int ccnt)
{
    constexpr int SN = 128 * D + 4;
    constexpr int C4N = 32 * D;
    constexpr int DN = NT / C4N;
    constexpr int DC = NT - DN * C4N;
    extern __shared__ unsigned char smem[];
    const uint32_t smem_u32 = (uint32_t)__cvta_generic_to_shared(smem);
    const uint32_t AS  = smem_u32;                 // single A buffer
    const uint32_t MIR = smem_u32 + OFF_MIR;
    const uint32_t WS  = smem_u32;                 // W staged over A+mirror union
    const float* mirf = reinterpret_cast<const float*>(smem + OFF_MIR);
    __half* Wp   = reinterpret_cast<__half*>(smem);
    float* stage = reinterpret_cast<float*>(smem + OFF_STG);
    const int tid = threadIdx.x;

    const int ntiles = (ntot * D + 31) >> 5;
    const int nloc = (ntiles - cidx + ccnt - 1) / ccnt;
    if (nloc <= 0) return;

    // ---- Prologue: stage W^T fp16 (ALPHA folded) over the A/mirror union ----
    for (int idx = tid; idx < 128 * 128; idx += NT) {
        int u = idx >> 7, ww = idx & 127;
        Wp[ww * PLE + u] = __float2half_rn(w[idx] * ALPHA_F);
    }
    __syncthreads();

    // ---- Warp geometry: 4 warps, tile m32 x n32 (all warps m0=0) ----
    const int warp = tid >> 5;
    const int lane = tid & 31;
    const int n0 = warp * 32;
    const int arow = (lane & 7) | (lane & 8);
    const int akc  = (lane >> 4) << 3;
    const int brow = (lane & 7) | ((lane & 16) >> 1);
    const int bkc  = lane & 8;
    int aoff[2];
#pragma unroll
    for (int mi = 0; mi < 2; mi++)
        aoff[mi] = ((mi * 16 + arow) * PLE + akc) * 2;

    // ---- Load ALL W fragments into registers (constant across tiles) ----
    uint32_t wr[64];
#pragma unroll
    for (int ks = 0; ks < 8; ks++)
#pragma unroll
        for (int jc = 0; jc < 2; jc++)
            ldmx4(&wr[ks * 8 + jc * 4],
                  WS + (uint32_t)(((n0 + jc * 16 + brow) * PLE + bkc) * 2 + ks * 32));
    __syncthreads();   // W region free -> A buffer + mirror usable

    // ---- First tile: gather + convert (one-time exposed latency) ----
    issue_mirror<D, OFF>(MIR, x, cidx, ntot, tid);
    asm volatile("cp.async.wait_group 0;\n");
    convert_tile<D>(AS, mirf, cidx, tid);
    __syncthreads();

    const int g = lane >> 2, tq = lane & 3;

    for (int j = 0; j < nloc; j++) {
        const int kt = cidx + j * ccnt;
        const int r0 = kt << 5;
        const int en0 = r0 / D;
        int en1 = (r0 + 31) / D + 1; if (en1 > ntot) en1 = ntot;

        // ---- Issue next tile's gather (covered by mainloop + epi1) ----
        if (j + 1 < nloc)
            issue_mirror<D, OFF>(MIR, x, cidx + (j + 1) * ccnt, ntot, tid);

        // ---- MMA mainloop: 2 ldmatrix + 8 HMMA per k-step ----
        float acc[2][4][4];
#pragma unroll
        for (int mi = 0; mi < 2; mi++)
#pragma unroll
            for (int jn = 0; jn < 4; jn++)
#pragma unroll
                for (int r = 0; r < 4; r++) acc[mi][jn][r] = 0.0f;

#pragma unroll
        for (int ks = 0; ks < 8; ks++) {
            const int kb2 = ks * 32;
            uint32_t a0[4], a1[4];
            ldmx4(a0, AS + aoff[0] + kb2);
            ldmx4(a1, AS + aoff[1] + kb2);
#pragma unroll
            for (int jc = 0; jc < 2; jc++) {
                const uint32_t* bw = &wr[ks * 8 + jc * 4];
                mma16816h(acc[0][2 * jc],     a0, bw[0], bw[1]);
                mma16816h(acc[1][2 * jc],     a1, bw[0], bw[1]);
                mma16816h(acc[0][2 * jc + 1], a0, bw[2], bw[3]);
                mma16816h(acc[1][2 * jc + 1], a1, bw[2], bw[3]);
            }
        }

        // ---- Epilogue 1: acc -> stage in x-layout (stage[nnloc][cc]) ----
        int rbase[4];
#pragma unroll
        for (int q = 0; q < 4; q++) {
            const int row = (q >> 1) * 16 + g + (q & 1) * 8;
            const int gr = r0 + row;
            const int nq = gr / D;
            rbase[q] = (nq - en0) * SN + (gr - nq * D);
        }
#pragma unroll
        for (int mi = 0; mi < 2; mi++) {
#pragma unroll
            for (int jn = 0; jn < 4; jn++) {
                const int col = n0 + 8 * jn + 2 * tq;
                if (D == 1) {
                    *reinterpret_cast<float2*>(stage + rbase[2 * mi] + col) =
                        make_float2(acc[mi][jn][0], acc[mi][jn][1]);
                    *reinterpret_cast<float2*>(stage + rbase[2 * mi + 1] + col) =
                        make_float2(acc[mi][jn][2], acc[mi][jn][3]);
                } else {
                    stage[rbase[2 * mi] + col * D]           = acc[mi][jn][0];
                    stage[rbase[2 * mi] + (col + 1) * D]     = acc[mi][jn][1];
                    stage[rbase[2 * mi + 1] + col * D]       = acc[mi][jn][2];
                    stage[rbase[2 * mi + 1] + (col + 1) * D] = acc[mi][jn][3];
                }
            }
        }
        __syncthreads();                           // S1: stage done, A reads done
        asm volatile("cp.async.wait_group 0;\n");  // this thread's gathers landed

        // ---- Merged phase: epi2 (stage -> gmem) + convert(j+1 -> A) ----
        {
            const int last = en1 - en0 - 1;
            const int et = (en1 - en0) * C4N;
            int nnr = tid / C4N;
            int c4 = tid - nnr * C4N;
            for (int t = tid; t < et; t += NT) {
                const int nn = en0 + nnr;
                float* gp = out + (long)nn * FEATS + OFF + 4 * c4;
                const float* sp = stage + nnr * SN + 4 * c4;
                if (D == 1) {
                    *reinterpret_cast<float4*>(gp) =
                        *reinterpret_cast<const float4*>(sp);
                } else {
                    const bool edge = (nnr == 0) | (nnr == last);
                    if (!edge) {
                        *reinterpret_cast<float4*>(gp) =
                            *reinterpret_cast<const float4*>(sp);
                    } else {
                        int u = (4 * c4) / D;
                        int ii = 4 * c4 - u * D;
#pragma unroll
                        for (int e = 0; e < 4; e++) {
                            const int rr = nn * D + ii - r0;
                            if ((unsigned)rr < 32u) gp[e] = sp[e];
                            if (++ii == D) { ii = 0; u++; }
                        }
                    }
                }
                nnr += DN; c4 += DC;
                if (c4 >= C4N) { c4 -= C4N; nnr++; }
            }
        }
        if (j + 1 < nloc)
            convert_tile<D>(AS, mirf, cidx + (j + 1) * ccnt, tid);
        __syncthreads();   // S2: stage consumed, A(j+1) ready, mirror free
    }
}

__global__ __launch_bounds__(NT, 4)
void Linear_36146444763339_kernel(
    const float* __restrict__ x,
    const float* __restrict__ w0,
    const float* __restrict__ w1,
    const float* __restrict__ w2,
    float* __restrict__ out,
    int ntot)
{
    const int bx = blockIdx.x;
    if (bx < 66)       run_block<1, 0>  (x, w0, out, ntot, bx,       66);
    else if (bx < 263) run_block<3, 128>(x, w1, out, ntot, bx - 66,  197);
    else               run_block<5, 512>(x, w2, out, ntot, bx - 263, 329);
}

extern "C" void kernel_launch(void* const* d_in, const int* in_sizes, int n_in,
                              void* d_out, int out_size) {
    const float* x  = (const float*)d_in[0];
    const float* w0 = (const float*)d_in[1];
    const float* w1 = (const float*)d_in[2];
    const float* w2 = (const float*)d_in[3];
    float* out = (float*)d_out;
    const int ntot = in_sizes[0] / FEATS;

    cudaFuncSetAttribute(Linear_36146444763339_kernel,
                         cudaFuncAttributeMaxDynamicSharedMemorySize, SMEM_BYTES);

    Linear_36146444763339_kernel<<<592, NT, SMEM_BYTES>>>(x, w0, w1, w2, out, ntot);
}